// round 2
// baseline (speedup 1.0000x reference)
#include <cuda_runtime.h>

// ---------------- problem constants ----------------
#define N_NODES 100000
#define HID     256     // TRACE_HID
#define MV      128     // MVC_DIM
#define MH      64      // MVC_HID
#define NE      1600000
#define NE3     4800000

// per-node precomputed A = Wfc1[:, :128] @ mvc_norm, B = Wfc1[:, 128:] @ mvc_norm
__device__ float g_A[(size_t)N_NODES * 64];
__device__ float g_B[(size_t)N_NODES * 64];

#define BN  64      // nodes per block
#define TPB 256
#define KC  32      // k-chunk for weight staging

// ---- shared memory layout (floats) ----
// xs : [256][68]  X tile transposed (k, node)   -- reused as ws3 [128][132] for GEMM3
// hs : [256][68]  h tile transposed (k, node)
// mvs: [128][68]  mvc tile transposed (col, node)
// ws : [32][257]  staged weight k-chunk (kk, outcol)
// red: [4][64] + nrm[64]
constexpr int XS_OFF  = 0;
constexpr int XS_SZ   = 256 * 68;            // 17408
constexpr int HS_OFF  = XS_OFF + XS_SZ;
constexpr int HS_SZ   = 256 * 68;            // 17408
constexpr int MV_OFF  = HS_OFF + HS_SZ;
constexpr int MV_SZ   = 128 * 68;            // 8704
constexpr int WS_OFF  = MV_OFF + MV_SZ;
constexpr int WS_SZ   = 32 * 257;            // 8224
constexpr int RED_OFF = WS_OFF + WS_SZ;
constexpr int RED_SZ  = 4 * 64 + 64;         // 320
constexpr int SMEM_FLOATS = RED_OFF + RED_SZ;
constexpr int SMEM_BYTES  = SMEM_FLOATS * 4; // 208256 B

// =====================================================================
// Node kernel: per 64-node tile, fully fused
//   x(256) -> h = relu(Wlin x)(256) -> mvc = Wlin2 h (128) -> normalize
//   -> A = Wfc1[:, :128] mvc, B = Wfc1[:, 128:] mvc  -> g_A, g_B
// =====================================================================
__global__ void __launch_bounds__(TPB, 1) node_kernel(
    const float* __restrict__ trace,   // (2, N, 128)
    const float* __restrict__ Wlin,    // (256, 256)
    const float* __restrict__ Wlin2,   // (128, 256)
    const float* __restrict__ Wfc1)    // (64, 256)
{
    extern __shared__ float sm[];
    float* xs  = sm + XS_OFF;    // [k][68]
    float* hs  = sm + HS_OFF;    // [k][68]
    float* mvs = sm + MV_OFF;    // [c][68]
    float* ws  = sm + WS_OFF;    // [kk][257]
    float* red = sm + RED_OFF;   // [4][64]
    float* nrm = red + 256;      // [64]

    const int t    = threadIdx.x;
    const int lane = t & 31;
    const int w    = t >> 5;
    const int n0   = blockIdx.x * BN;

    // ---- load X tile: xs[k][n] = concat(trace[0][n], trace[1][n])[k] ----
    #pragma unroll
    for (int i = 0; i < 8; i++) {
        int nl = w * 8 + i;
        int n  = n0 + nl;
        #pragma unroll
        for (int j = 0; j < 8; j++) {
            int k = lane + 32 * j;
            float v = 0.0f;
            if (n < N_NODES) {
                v = (k < 128) ? trace[(size_t)n * 128 + k]
                              : trace[(size_t)(N_NODES + n) * 128 + (k - 128)];
            }
            xs[k * 68 + nl] = v;
        }
    }
    __syncthreads();

    // ---------------- GEMM1: h[c][n] = relu(sum_k Wlin[c][k] * x[n][k]) ----------------
    // thread t owns output column c = t over all 64 nodes
    {
        float acc[64];
        #pragma unroll
        for (int i = 0; i < 64; i++) acc[i] = 0.0f;

        for (int k0 = 0; k0 < 256; k0 += KC) {
            __syncthreads();
            // stage ws[kk][c2] = Wlin[c2][k0+kk]; each warp handles rows c2 = w + 8r
            #pragma unroll 4
            for (int r = 0; r < 32; r++) {
                int c2 = w + 8 * r;
                ws[lane * 257 + c2] = Wlin[c2 * 256 + k0 + lane];
            }
            __syncthreads();
            #pragma unroll
            for (int kk = 0; kk < KC; kk++) {
                float wv = ws[kk * 257 + t];
                const float4* xr = (const float4*)(xs + (k0 + kk) * 68);
                #pragma unroll
                for (int q = 0; q < 16; q++) {
                    float4 x4 = xr[q];
                    acc[4*q+0] += wv * x4.x;
                    acc[4*q+1] += wv * x4.y;
                    acc[4*q+2] += wv * x4.z;
                    acc[4*q+3] += wv * x4.w;
                }
            }
        }
        __syncthreads();
        float4* hr = (float4*)(hs + t * 68);
        #pragma unroll
        for (int q = 0; q < 16; q++) {
            float4 v;
            v.x = fmaxf(acc[4*q+0], 0.0f);
            v.y = fmaxf(acc[4*q+1], 0.0f);
            v.z = fmaxf(acc[4*q+2], 0.0f);
            v.w = fmaxf(acc[4*q+3], 0.0f);
            hr[q] = v;
        }
    }
    __syncthreads();

    // ---------------- GEMM2: mvc[c][n] = sum_k Wlin2[c][k] * h[n][k] ----------------
    // thread: c = t & 127 over nodes half*32..half*32+31
    const int c    = t & 127;
    const int half = t >> 7;
    {
        float acc2[32];
        #pragma unroll
        for (int i = 0; i < 32; i++) acc2[i] = 0.0f;

        for (int k0 = 0; k0 < 256; k0 += KC) {
            __syncthreads();
            #pragma unroll 4
            for (int r = 0; r < 16; r++) {
                int c2 = w + 8 * r;
                ws[lane * 257 + c2] = Wlin2[c2 * 256 + k0 + lane];
            }
            __syncthreads();
            #pragma unroll
            for (int kk = 0; kk < KC; kk++) {
                float wv = ws[kk * 257 + c];
                const float4* hr = (const float4*)(hs + (k0 + kk) * 68 + half * 32);
                #pragma unroll
                for (int q = 0; q < 8; q++) {
                    float4 h4 = hr[q];
                    acc2[4*q+0] += wv * h4.x;
                    acc2[4*q+1] += wv * h4.y;
                    acc2[4*q+2] += wv * h4.z;
                    acc2[4*q+3] += wv * h4.w;
                }
            }
        }
        __syncthreads();
        #pragma unroll
        for (int i = 0; i < 32; i++) mvs[c * 68 + half * 32 + i] = acc2[i];
    }
    __syncthreads();

    // ---------------- row norm + normalize ----------------
    {
        int n = t & 63, part = t >> 6;
        float s = 0.0f;
        #pragma unroll 4
        for (int cc = part * 32; cc < part * 32 + 32; cc++) {
            float v = mvs[cc * 68 + n];
            s += v * v;
        }
        red[part * 64 + n] = s;
        __syncthreads();
        if (t < 64) {
            float ss = red[t] + red[64 + t] + red[128 + t] + red[192 + t];
            nrm[t] = fmaxf(sqrtf(ss), 1e-12f);
        }
        __syncthreads();
        for (int idx = t; idx < 128 * 64; idx += TPB) {
            int cc = idx >> 6, n2 = idx & 63;
            mvs[cc * 68 + n2] = mvs[cc * 68 + n2] / nrm[n2];
        }
    }
    __syncthreads();

    // ---------------- GEMM3: [A;B][j][n] = sum_k Cw[j][k] * mvc_norm[k][n] ----------------
    // Cw[j][k] = Wfc1[j][k] for j<64 ; Wfc1[j-64][128+k] for j>=64
    float* ws3 = xs;  // reuse xs region: [k][132], 128x132 floats
    {
        #pragma unroll 4
        for (int r = 0; r < 16; r++) {
            int j = w + 8 * r;
            int jj = j & 63;
            int koff = (j >= 64) ? 128 : 0;
            #pragma unroll
            for (int q = 0; q < 4; q++) {
                int k = lane + 32 * q;
                ws3[k * 132 + j] = Wfc1[jj * 256 + koff + k];
            }
        }
    }
    __syncthreads();
    {
        const int j = c;  // t & 127
        float acc3[32];
        #pragma unroll
        for (int i = 0; i < 32; i++) acc3[i] = 0.0f;

        #pragma unroll 2
        for (int k = 0; k < 128; k++) {
            float wv = ws3[k * 132 + j];
            const float4* mr = (const float4*)(mvs + k * 68 + half * 32);
            #pragma unroll
            for (int q = 0; q < 8; q++) {
                float4 m4 = mr[q];
                acc3[4*q+0] += wv * m4.x;
                acc3[4*q+1] += wv * m4.y;
                acc3[4*q+2] += wv * m4.z;
                acc3[4*q+3] += wv * m4.w;
            }
        }
        // write out: coalesced across j within warp
        #pragma unroll
        for (int i = 0; i < 32; i++) {
            int n = n0 + half * 32 + i;
            if (n < N_NODES) {
                if (j < 64) g_A[(size_t)n * 64 + j]        = acc3[i];
                else        g_B[(size_t)n * 64 + (j - 64)] = acc3[i];
            }
        }
    }
}

// =====================================================================
// Edge kernel: per edge e
//   h2 = relu(A[src] + B[dst] + b_fc1); s0 = w0.h2 + b2_0; s1 = w1.h2 + b2_1
//   active = ((s0+g0) >= (s1+g1)); out[e]=active; out[NE+e]=out[2NE+e]=1-active
// =====================================================================
__global__ void __launch_bounds__(256) edge_kernel(
    const int*   __restrict__ ei,      // (2, 3*NE)
    const float* __restrict__ gum,     // (NE, 2)
    const float* __restrict__ Wfc2,    // (2, 64)
    const float* __restrict__ bfc2,    // (2,)
    const float* __restrict__ bfc1,    // (64,)
    float*       __restrict__ out)     // (3*NE,)
{
    __shared__ float w0[64], w1[64], bb[64], b2s[2];
    int t = threadIdx.x;
    if (t < 64) { w0[t] = Wfc2[t]; w1[t] = Wfc2[64 + t]; bb[t] = bfc1[t]; }
    if (t < 2)  { b2s[t] = bfc2[t]; }
    __syncthreads();

    int e = blockIdx.x * 256 + t;
    if (e >= NE) return;

    int src = ei[e];
    int dst = ei[NE3 + e];

    const float4* ap = (const float4*)(g_A + (size_t)src * 64);
    const float4* bp = (const float4*)(g_B + (size_t)dst * 64);
    const float4* biv = (const float4*)bb;
    const float4* w0v = (const float4*)w0;
    const float4* w1v = (const float4*)w1;

    float s0 = 0.0f, s1 = 0.0f;
    #pragma unroll
    for (int q = 0; q < 16; q++) {
        float4 a = ap[q], b = bp[q], bi = biv[q], u = w0v[q], v = w1v[q];
        float r;
        r = fmaxf(a.x + b.x + bi.x, 0.0f); s0 += u.x * r; s1 += v.x * r;
        r = fmaxf(a.y + b.y + bi.y, 0.0f); s0 += u.y * r; s1 += v.y * r;
        r = fmaxf(a.z + b.z + bi.z, 0.0f); s0 += u.z * r; s1 += v.z * r;
        r = fmaxf(a.w + b.w + bi.w, 0.0f); s0 += u.w * r; s1 += v.w * r;
    }
    s0 += b2s[0];
    s1 += b2s[1];

    float2 g = ((const float2*)gum)[e];
    float active = ((s0 + g.x) >= (s1 + g.y)) ? 1.0f : 0.0f;

    out[e]          = active;
    out[NE + e]     = 1.0f - active;
    out[2 * NE + e] = 1.0f - active;
}

// =====================================================================
extern "C" void kernel_launch(void* const* d_in, const int* in_sizes, int n_in,
                              void* d_out, int out_size)
{
    const float* trace = (const float*)d_in[0];  // trace_all (2,100000,128)
    const float* Wlin  = (const float*)d_in[1];  // (256,256)
    const float* Wlin2 = (const float*)d_in[2];  // (128,256)
    const float* Wfc1  = (const float*)d_in[3];  // (64,256)
    const float* bfc1  = (const float*)d_in[4];  // (64,)
    const float* Wfc2  = (const float*)d_in[5];  // (2,64)
    const float* bfc2  = (const float*)d_in[6];  // (2,)
    const float* gum   = (const float*)d_in[7];  // (NE,2)
    const int*   ei    = (const int*)d_in[8];    // (2,3*NE)
    // d_in[9] = num_edge (constant NE)

    cudaFuncSetAttribute(node_kernel,
                         cudaFuncAttributeMaxDynamicSharedMemorySize, SMEM_BYTES);

    int nblocks = (N_NODES + BN - 1) / BN;   // 1563
    node_kernel<<<nblocks, TPB, SMEM_BYTES>>>(trace, Wlin, Wlin2, Wfc1);

    int eblocks = (NE + 255) / 256;          // 6250
    edge_kernel<<<eblocks, 256>>>(ei, gum, Wfc2, bfc2, bfc1, (float*)d_out);
}

// round 5
// speedup vs baseline: 1.7443x; 1.7443x over previous
#include <cuda_runtime.h>

// ---------------- problem constants ----------------
#define N_NODES 100000
#define NE      1600000
#define NE3     4800000

// per-node precomputed A = Wfc1[:, :128] @ mvc_norm, B = Wfc1[:, 128:] @ mvc_norm
__device__ __align__(16) float g_A[(size_t)N_NODES * 64];
__device__ __align__(16) float g_B[(size_t)N_NODES * 64];

#define BN  64      // nodes per block
#define TPB 512
#define KC  32      // k-chunk for weight staging

// ---- shared memory layout (floats) ----
constexpr int XS_OFF  = 0;
constexpr int XS_SZ   = 256 * 68;            // X tile [k][68]; reused as ws3 [128][132]
constexpr int HS_OFF  = XS_OFF + XS_SZ;
constexpr int HS_SZ   = 256 * 68;            // h tile [c][68]
constexpr int MV_OFF  = HS_OFF + HS_SZ;
constexpr int MV_SZ   = 128 * 68;            // mvc tile [c][68]
constexpr int WS_OFF  = MV_OFF + MV_SZ;
constexpr int WS_SZ   = 32 * 257;            // staged weights [kk][257]
constexpr int RED_OFF = WS_OFF + WS_SZ;
constexpr int RED_SZ  = 8 * 64 + 64;         // reduction + norms
constexpr int SMEM_FLOATS = RED_OFF + RED_SZ;
constexpr int SMEM_BYTES  = SMEM_FLOATS * 4; // ~209 KB

// ---------------- packed fp32x2 helpers (sm_103a) ----------------
__device__ __forceinline__ unsigned long long pack2(float v) {
    unsigned long long r;
    asm("mov.b64 %0, {%1, %1};" : "=l"(r) : "f"(v));
    return r;
}
__device__ __forceinline__ void ffma2(unsigned long long& d,
                                      unsigned long long a,
                                      unsigned long long b) {
    asm("fma.rn.f32x2 %0, %1, %2, %0;" : "+l"(d) : "l"(a), "l"(b));
}
__device__ __forceinline__ float2 unpack2(unsigned long long v) {
    float2 f;
    asm("mov.b64 {%0, %1}, %2;" : "=f"(f.x), "=f"(f.y) : "l"(v));
    return f;
}

// =====================================================================
// Node kernel: per 64-node tile, fully fused, packed f32x2 FMAs.
//   x(256) -> h = relu(Wlin x) -> mvc = Wlin2 h -> normalize
//   -> A = Wfc1[:, :128] mvc, B = Wfc1[:, 128:] mvc  -> g_A, g_B
// =====================================================================
__global__ void __launch_bounds__(TPB, 1) node_kernel(
    const float* __restrict__ trace,   // (2, N, 128)
    const float* __restrict__ Wlin,    // (256, 256)
    const float* __restrict__ Wlin2,   // (128, 256)
    const float* __restrict__ Wfc1)    // (64, 256)
{
    extern __shared__ float sm[];
    float* xs  = sm + XS_OFF;    // [k][68]
    float* hs  = sm + HS_OFF;    // [c][68]
    float* mvs = sm + MV_OFF;    // [c][68]
    float* ws  = sm + WS_OFF;    // [kk][257]
    float* red = sm + RED_OFF;   // [8][64]
    float* nrm = red + 512;      // [64]

    const int t    = threadIdx.x;
    const int lane = t & 31;
    const int w    = t >> 5;     // 0..15
    const int n0   = blockIdx.x * BN;

    // ---- load X tile: xs[k][n] = concat(trace[0][n], trace[1][n])[k] ----
    #pragma unroll
    for (int i = 0; i < 4; i++) {
        int nl = w * 4 + i;
        int n  = n0 + nl;
        #pragma unroll
        for (int j = 0; j < 8; j++) {
            int k = lane + 32 * j;
            float v = 0.0f;
            if (n < N_NODES) {
                v = (k < 128) ? trace[(size_t)n * 128 + k]
                              : trace[(size_t)(N_NODES + n) * 128 + (k - 128)];
            }
            xs[k * 68 + nl] = v;
        }
    }

    // ---------------- GEMM1: h[c][n] = relu(sum_k Wlin[c][k] * x[k][n]) ----------------
    // thread: cols {c0, c0+128}, 16 nodes (quarter)
    {
        const int c0 = t & 127;
        const int nn = (t >> 7) * 16;
        unsigned long long a0[8], a1[8];
        #pragma unroll
        for (int i = 0; i < 8; i++) { a0[i] = 0ull; a1[i] = 0ull; }

        for (int k0 = 0; k0 < 256; k0 += KC) {
            __syncthreads();
            #pragma unroll
            for (int r = 0; r < 16; r++) {
                int c2 = w + 16 * r;
                ws[lane * 257 + c2] = Wlin[c2 * 256 + k0 + lane];
            }
            __syncthreads();
            #pragma unroll
            for (int kk = 0; kk < KC; kk++) {
                unsigned long long wv0 = pack2(ws[kk * 257 + c0]);
                unsigned long long wv1 = pack2(ws[kk * 257 + c0 + 128]);
                const ulonglong2* xr =
                    (const ulonglong2*)(xs + (k0 + kk) * 68 + nn);
                #pragma unroll
                for (int q = 0; q < 4; q++) {
                    ulonglong2 x2 = xr[q];
                    ffma2(a0[2*q],   wv0, x2.x);
                    ffma2(a0[2*q+1], wv0, x2.y);
                    ffma2(a1[2*q],   wv1, x2.x);
                    ffma2(a1[2*q+1], wv1, x2.y);
                }
            }
        }
        // relu + store h (transposed [c][n])
        float4* h0 = (float4*)(hs + c0 * 68 + nn);
        float4* h1 = (float4*)(hs + (c0 + 128) * 68 + nn);
        #pragma unroll
        for (int q = 0; q < 4; q++) {
            float2 p = unpack2(a0[2*q]), r2 = unpack2(a0[2*q+1]);
            float4 v;
            v.x = fmaxf(p.x, 0.f);  v.y = fmaxf(p.y, 0.f);
            v.z = fmaxf(r2.x, 0.f); v.w = fmaxf(r2.y, 0.f);
            h0[q] = v;
            p = unpack2(a1[2*q]); r2 = unpack2(a1[2*q+1]);
            v.x = fmaxf(p.x, 0.f);  v.y = fmaxf(p.y, 0.f);
            v.z = fmaxf(r2.x, 0.f); v.w = fmaxf(r2.y, 0.f);
            h1[q] = v;
        }
    }

    // ---------------- GEMM2: mvc[c][n] = sum_k Wlin2[c][k] * h[k][n] ----------------
    // thread: cols {d0, d0+64}, 8 nodes (oct)
    {
        const int d0 = t & 63;
        const int on = (t >> 6) * 8;
        unsigned long long a0[4], a1[4];
        #pragma unroll
        for (int i = 0; i < 4; i++) { a0[i] = 0ull; a1[i] = 0ull; }

        for (int k0 = 0; k0 < 256; k0 += KC) {
            __syncthreads();   // also orders hs writes before hs reads (first iter)
            #pragma unroll
            for (int r = 0; r < 8; r++) {
                int c2 = w + 16 * r;
                ws[lane * 257 + c2] = Wlin2[c2 * 256 + k0 + lane];
            }
            __syncthreads();
            #pragma unroll
            for (int kk = 0; kk < KC; kk++) {
                unsigned long long wv0 = pack2(ws[kk * 257 + d0]);
                unsigned long long wv1 = pack2(ws[kk * 257 + d0 + 64]);
                const ulonglong2* hr =
                    (const ulonglong2*)(hs + (k0 + kk) * 68 + on);
                #pragma unroll
                for (int q = 0; q < 2; q++) {
                    ulonglong2 h2 = hr[q];
                    ffma2(a0[2*q],   wv0, h2.x);
                    ffma2(a0[2*q+1], wv0, h2.y);
                    ffma2(a1[2*q],   wv1, h2.x);
                    ffma2(a1[2*q+1], wv1, h2.y);
                }
            }
        }
        float4* m0 = (float4*)(mvs + d0 * 68 + on);
        float4* m1 = (float4*)(mvs + (d0 + 64) * 68 + on);
        #pragma unroll
        for (int q = 0; q < 2; q++) {
            float2 p = unpack2(a0[2*q]), r2 = unpack2(a0[2*q+1]);
            m0[q] = make_float4(p.x, p.y, r2.x, r2.y);
            p = unpack2(a1[2*q]); r2 = unpack2(a1[2*q+1]);
            m1[q] = make_float4(p.x, p.y, r2.x, r2.y);
        }
    }
    __syncthreads();

    // ---------------- row norm + normalize ----------------
    {
        int n = t & 63, p = t >> 6;   // p: 0..7, 16 cols each
        float s = 0.0f;
        #pragma unroll 4
        for (int cc = p * 16; cc < p * 16 + 16; cc++) {
            float v = mvs[cc * 68 + n];
            s += v * v;
        }
        red[p * 64 + n] = s;
        __syncthreads();
        if (t < 64) {
            float ss = 0.0f;
            #pragma unroll
            for (int p2 = 0; p2 < 8; p2++) ss += red[p2 * 64 + t];
            nrm[t] = fmaxf(sqrtf(ss), 1e-12f);
        }
        __syncthreads();
        for (int idx = t; idx < 128 * 64; idx += TPB) {
            int cc = idx >> 6, n2 = idx & 63;
            mvs[cc * 68 + n2] = mvs[cc * 68 + n2] / nrm[n2];
        }
    }
    __syncthreads();

    // ---------------- GEMM3: [A;B][j][n] = sum_k Cw[j][k] * mvc_norm[k][n] ----------------
    float* ws3 = xs;  // reuse xs region: [k][132]
    {
        #pragma unroll
        for (int r = 0; r < 8; r++) {
            int j  = w + 16 * r;
            int jj = j & 63;
            int koff = (j >= 64) ? 128 : 0;
            #pragma unroll
            for (int q = 0; q < 4; q++) {
                int k = lane + 32 * q;
                ws3[k * 132 + j] = Wfc1[jj * 256 + koff + k];
            }
        }
    }
    __syncthreads();
    {
        const int j0 = t & 63;
        const int on = (t >> 6) * 8;
        unsigned long long aA[4], aB[4];
        #pragma unroll
        for (int i = 0; i < 4; i++) { aA[i] = 0ull; aB[i] = 0ull; }

        #pragma unroll 4
        for (int k = 0; k < 128; k++) {
            unsigned long long wv0 = pack2(ws3[k * 132 + j0]);
            unsigned long long wv1 = pack2(ws3[k * 132 + j0 + 64]);
            const ulonglong2* mr = (const ulonglong2*)(mvs + k * 68 + on);
            #pragma unroll
            for (int q = 0; q < 2; q++) {
                ulonglong2 m2 = mr[q];
                ffma2(aA[2*q],   wv0, m2.x);
                ffma2(aA[2*q+1], wv0, m2.y);
                ffma2(aB[2*q],   wv1, m2.x);
                ffma2(aB[2*q+1], wv1, m2.y);
            }
        }
        #pragma unroll
        for (int q = 0; q < 4; q++) {
            float2 pa = unpack2(aA[q]);
            float2 pb = unpack2(aB[q]);
            int n = n0 + on + 2 * q;
            if (n < N_NODES) {
                g_A[(size_t)n * 64 + j0] = pa.x;
                g_B[(size_t)n * 64 + j0] = pb.x;
            }
            if (n + 1 < N_NODES) {
                g_A[(size_t)(n + 1) * 64 + j0] = pa.y;
                g_B[(size_t)(n + 1) * 64 + j0] = pb.y;
            }
        }
    }
}

// =====================================================================
// Edge kernel: 8 threads per edge, coalesced 128B-line gathers.
//   h2 = relu(A[src] + B[dst] + b_fc1); s = Wfc2 h2 + b_fc2
//   active = ((s0+g0) >= (s1+g1)); out[e]=active; out[NE+e]=out[2NE+e]=1-active
// =====================================================================
#define EPB 256   // edges per block
__global__ void __launch_bounds__(256) edge_kernel(
    const int*   __restrict__ ei,      // (2, 3*NE)
    const float* __restrict__ gum,     // (NE, 2)
    const float* __restrict__ Wfc2,    // (2, 64)
    const float* __restrict__ bfc2,    // (2,)
    const float* __restrict__ bfc1,    // (64,)
    float*       __restrict__ out)     // (3*NE,)
{
    __shared__ float sact[EPB];
    const int t  = threadIdx.x;
    const int g  = t & 7;     // lane within 8-thread group
    const int gi = t >> 3;    // group id within block: 0..31

    // per-thread weight/bias slices: components {4g..4g+3, 32+4g..32+4g+3}
    float w0r[8], w1r[8], bbr[8];
    #pragma unroll
    for (int u = 0; u < 4; u++) {
        w0r[u]     = Wfc2[g * 4 + u];
        w0r[4 + u] = Wfc2[32 + g * 4 + u];
        w1r[u]     = Wfc2[64 + g * 4 + u];
        w1r[4 + u] = Wfc2[96 + g * 4 + u];
        bbr[u]     = bfc1[g * 4 + u];
        bbr[4 + u] = bfc1[32 + g * 4 + u];
    }
    const float c0 = bfc2[0], c1 = bfc2[1];
    const size_t e0 = (size_t)blockIdx.x * EPB;

    #pragma unroll
    for (int it = 0; it < EPB / 32; it++) {
        int    el = it * 32 + gi;
        size_t e  = e0 + el;

        int src = ei[e];
        int dst = ei[NE3 + e];
        const float4* ap = (const float4*)(g_A + (size_t)src * 64);
        const float4* bp = (const float4*)(g_B + (size_t)dst * 64);
        float4 a0 = ap[g], a1 = ap[8 + g];
        float4 b0 = bp[g], b1 = bp[8 + g];

        float s0 = 0.0f, s1 = 0.0f, r;
        r = fmaxf(a0.x + b0.x + bbr[0], 0.f); s0 = fmaf(w0r[0], r, s0); s1 = fmaf(w1r[0], r, s1);
        r = fmaxf(a0.y + b0.y + bbr[1], 0.f); s0 = fmaf(w0r[1], r, s0); s1 = fmaf(w1r[1], r, s1);
        r = fmaxf(a0.z + b0.z + bbr[2], 0.f); s0 = fmaf(w0r[2], r, s0); s1 = fmaf(w1r[2], r, s1);
        r = fmaxf(a0.w + b0.w + bbr[3], 0.f); s0 = fmaf(w0r[3], r, s0); s1 = fmaf(w1r[3], r, s1);
        r = fmaxf(a1.x + b1.x + bbr[4], 0.f); s0 = fmaf(w0r[4], r, s0); s1 = fmaf(w1r[4], r, s1);
        r = fmaxf(a1.y + b1.y + bbr[5], 0.f); s0 = fmaf(w0r[5], r, s0); s1 = fmaf(w1r[5], r, s1);
        r = fmaxf(a1.z + b1.z + bbr[6], 0.f); s0 = fmaf(w0r[6], r, s0); s1 = fmaf(w1r[6], r, s1);
        r = fmaxf(a1.w + b1.w + bbr[7], 0.f); s0 = fmaf(w0r[7], r, s0); s1 = fmaf(w1r[7], r, s1);

        // reduce across the 8-thread group
        #pragma unroll
        for (int m = 1; m < 8; m <<= 1) {
            s0 += __shfl_xor_sync(0xffffffff, s0, m);
            s1 += __shfl_xor_sync(0xffffffff, s1, m);
        }

        if (g == 0) {
            float2 gm = ((const float2*)gum)[e];
            sact[el] = ((s0 + c0 + gm.x) >= (s1 + c1 + gm.y)) ? 1.0f : 0.0f;
        }
    }
    __syncthreads();

    float a = sact[t];
    out[e0 + t]          = a;
    out[NE + e0 + t]     = 1.0f - a;
    out[2 * NE + e0 + t] = 1.0f - a;
}

// =====================================================================
extern "C" void kernel_launch(void* const* d_in, const int* in_sizes, int n_in,
                              void* d_out, int out_size)
{
    const float* trace = (const float*)d_in[0];  // (2,100000,128)
    const float* Wlin  = (const float*)d_in[1];  // (256,256)
    const float* Wlin2 = (const float*)d_in[2];  // (128,256)
    const float* Wfc1  = (const float*)d_in[3];  // (64,256)
    const float* bfc1  = (const float*)d_in[4];  // (64,)
    const float* Wfc2  = (const float*)d_in[5];  // (2,64)
    const float* bfc2  = (const float*)d_in[6];  // (2,)
    const float* gum   = (const float*)d_in[7];  // (NE,2)
    const int*   ei    = (const int*)d_in[8];    // (2,3*NE)

    cudaFuncSetAttribute(node_kernel,
                         cudaFuncAttributeMaxDynamicSharedMemorySize, SMEM_BYTES);

    int nblocks = (N_NODES + BN - 1) / BN;   // 1563
    node_kernel<<<nblocks, TPB, SMEM_BYTES>>>(trace, Wlin, Wlin2, Wfc1);

    int eblocks = NE / EPB;                  // 6250
    edge_kernel<<<eblocks, 256>>>(ei, gum, Wfc2, bfc2, bfc1, (float*)d_out);
}